// round 2
// baseline (speedup 1.0000x reference)
#include <cuda_runtime.h>
#include <cuda_bf16.h>
#include <math.h>

#define NGRID 128
#define NDIR  128
#define NK    25
#define NKP   28          // padded to float4 multiple
#define P_TOTAL (NGRID*NGRID*NGRID)
#define BLOCK 256

// out channel scale = pi^2 / (2*L*L) with true pi, L=8 -> pi^2/128
#define OUT_SCALE 0.07710628438351044f

__global__ __launch_bounds__(BLOCK)
void sh_nearfield_kernel(const float* __restrict__ bases,
                         const float* __restrict__ th,
                         const float* __restrict__ ph,
                         const int*   __restrict__ iternum_p,
                         int B,
                         float* __restrict__ out)
{
    __shared__ float4 dirs[NDIR];           // vx, vy, vz, sinth
    __shared__ float  basesT[NDIR * NKP];   // [d][k], padded rows (112B, 16B aligned)

    const int tid = threadIdx.x;

    // Fill direction table
    if (tid < NDIR) {
        float t = th[tid];
        float p = ph[tid];
        float st, ct, sp, cp;
        __sincosf(t, &st, &ct);     // fast sincos; th in (0, pi) well-conditioned
        // use accurate sin/cos to be safe on precision:
        st = sinf(t); ct = cosf(t); sp = sinf(p); cp = cosf(p);
        dirs[tid] = make_float4(st * sp, ct, st * cp, st);
    }
    // Fill transposed bases, zero pad
    for (int i = tid; i < NDIR * NKP; i += BLOCK) {
        int d = i / NKP;
        int k = i - d * NKP;
        basesT[i] = (k < NK) ? bases[k * NDIR + d] : 0.0f;
    }
    __syncthreads();

    const int b = blockIdx.z;
    const int p = blockIdx.x * BLOCK + tid;

    // point coordinates: p = (iz*128 + iy)*128 + ix ; coord = -1 + 2*i/127
    const int ix = p & (NGRID - 1);
    const int iy = (p >> 7) & (NGRID - 1);
    const int iz = p >> 14;
    const float step = 2.0f / 127.0f;
    const float x = -1.0f + ix * step;
    const float y = -1.0f + iy * step;
    const float z = -1.0f + iz * step;

    // light position (PI_SRC = 3.1415926 truncated pi, per source)
    const int iternum = *iternum_p;
    const float ph0 = (float)((double)(iternum * B + b) * 2.0 * 3.1415926 / 131.0);
    const float lx = sinf(ph0) * 0.3f;
    const float ly = 0.0f;
    const float lz = 0.4f;

    const float ldx = lx - x;
    const float ldy = ly - y;
    const float ldz = lz - z;
    const float s  = fmaf(ldx, ldx, fmaf(ldy, ldy, fmaf(ldz, ldz, 1e-4f))); // norm^2 (pre-sqrt arg)
    const float rn = rsqrtf(s);
    const float nx = ldx * rn;
    const float ny = ldy * rn;
    const float nz = ldz * rn;

    // ---- Pass 1: sum over directions ----
    float sum = 0.0f;
    #pragma unroll 4
    for (int d = 0; d < NDIR; ++d) {
        float4 v = dirs[d];
        float dp = fmaf(v.x, nx, fmaf(v.y, ny, v.z * nz));
        dp = fminf(fmaxf(dp, -0.999f), 0.999f);
        float a = acosf(dp);
        float w = __expf(-16.0f * a * a) * v.w;
        sum += w;
    }

    const float invs = 4.0f / (s * sum);   // 4/(norm^2 * sum)

    // ---- Pass 2: recompute w, take log, project onto bases ----
    float acc[NK];
    #pragma unroll
    for (int k = 0; k < NK; ++k) acc[k] = 0.0f;

    #pragma unroll 1
    for (int d = 0; d < NDIR; ++d) {
        float4 v = dirs[d];
        float dp = fmaf(v.x, nx, fmaf(v.y, ny, v.z * nz));
        dp = fminf(fmaxf(dp, -0.999f), 0.999f);
        float a = acosf(dp);
        float w = __expf(-16.0f * a * a) * v.w;
        float lg = __logf(fmaf(w, invs, 1e-4f));

        const float4* row = (const float4*)&basesT[d * NKP];
        float bb[NKP];
        #pragma unroll
        for (int q = 0; q < NKP / 4; ++q) {
            float4 r4 = row[q];
            bb[4 * q + 0] = r4.x;
            bb[4 * q + 1] = r4.y;
            bb[4 * q + 2] = r4.z;
            bb[4 * q + 3] = r4.w;
        }
        #pragma unroll
        for (int k = 0; k < NK; ++k) acc[k] = fmaf(bb[k], lg, acc[k]);
    }

    // ---- Write output: channel j = k*3 + c, value replicated over c ----
    const size_t PP = (size_t)P_TOTAL;
    float* ob = out + (size_t)b * 75 * PP + p;
    #pragma unroll
    for (int k = 0; k < NK; ++k) {
        float v = acc[k] * OUT_SCALE;
        ob[(size_t)(3 * k + 0) * PP] = v;
        ob[(size_t)(3 * k + 1) * PP] = v;
        ob[(size_t)(3 * k + 2) * PP] = v;
    }
}

extern "C" void kernel_launch(void* const* d_in, const int* in_sizes, int n_in,
                              void* d_out, int out_size)
{
    const float* bases = (const float*)d_in[0];
    const float* th    = (const float*)d_in[1];
    const float* ph    = (const float*)d_in[2];
    const int*   itn   = (const int*)d_in[3];   // first 4 bytes valid for i32 or i64
    const int    B     = in_sizes[4];           // lightid element count

    dim3 grid(P_TOTAL / BLOCK, 1, (unsigned)B);
    sh_nearfield_kernel<<<grid, BLOCK>>>(bases, th, ph, itn, B, (float*)d_out);
}

// round 3
// speedup vs baseline: 1.3553x; 1.3553x over previous
#include <cuda_runtime.h>
#include <cuda_bf16.h>
#include <math.h>

#define NGRID 128
#define NDIR  128
#define NK    25
#define NKP   28          // row stride (floats), 112B = 16B aligned
#define P_TOTAL (NGRID*NGRID*NGRID)
#define BLOCK 256

// (pi^2/128) * ln(2)  -- output scale folded with log2->ln conversion
#define SCALE_LN2  0.05344600f
// 16 * log2(e)
#define K16LOG2E   23.0831207f

// q(x) ~ acos(x)^2 / (1-x), degree-9 (squared A&S 4.4.45 coefficients)
#define C0  2.4674011f
#define C1 -0.6741820f
#define C2  0.3255883f
#define C3 -0.1958168f
#define C4  0.1265018f
#define C5 -0.0758715f
#define C6  0.0363039f
#define C7 -0.0129701f
#define C8  0.0043979f
#define C9 -0.0019498f

__device__ __forceinline__ float ex2f(float x) {
    float r; asm("ex2.approx.ftz.f32 %0, %1;" : "=f"(r) : "f"(x)); return r;
}
__device__ __forceinline__ float lg2f(float x) {
    float r; asm("lg2.approx.ftz.f32 %0, %1;" : "=f"(r) : "f"(x)); return r;
}
__device__ __forceinline__ unsigned long long pack2(float lo, float hi) {
    unsigned long long r;
    asm("mov.b64 %0, {%1, %2};" : "=l"(r) : "f"(lo), "f"(hi));
    return r;
}
__device__ __forceinline__ void unpack2(unsigned long long v, float& lo, float& hi) {
    asm("mov.b64 {%0, %1}, %2;" : "=f"(lo), "=f"(hi) : "l"(v));
}
__device__ __forceinline__ unsigned long long fma2(unsigned long long a,
                                                   unsigned long long b,
                                                   unsigned long long c) {
    unsigned long long d;
    asm("fma.rn.f32x2 %0, %1, %2, %3;" : "=l"(d) : "l"(a), "l"(b), "l"(c));
    return d;
}

// Shared-path weight: returns exp2( -16*log2e * acos(clip(dp))^2 + log2(sinth) )
//                   = exp(-16*acos(clip(dp))^2) * sinth
__device__ __forceinline__ float dir_weight(float dp, float lsw) {
    float xc = fminf(dp, 0.999f);           // lower clip unnecessary (weight ~0 there)
    float q  = fmaf(C9, xc, C8);
    q = fmaf(q, xc, C7);
    q = fmaf(q, xc, C6);
    q = fmaf(q, xc, C5);
    q = fmaf(q, xc, C4);
    q = fmaf(q, xc, C3);
    q = fmaf(q, xc, C2);
    q = fmaf(q, xc, C1);
    q = fmaf(q, xc, C0);
    float u   = fmaf(xc, K16LOG2E, -K16LOG2E);  // -16*log2e*(1-xc)
    float arg = fmaf(u, q, lsw);
    return ex2f(arg);
}

__global__ __launch_bounds__(BLOCK)
void sh_nearfield_kernel(const float* __restrict__ bases,
                         const float* __restrict__ th,
                         const float* __restrict__ ph,
                         const int*   __restrict__ iternum_p,
                         int B,
                         float* __restrict__ out)
{
    __shared__ float4 dirs[NDIR];                       // vx, vy, vz, log2(sinth)
    __shared__ __align__(16) float basesT[NDIR * NKP];  // [d][k] padded rows

    const int tid = threadIdx.x;

    if (tid < NDIR) {
        float t = th[tid];
        float p = ph[tid];
        float st = sinf(t), ct = cosf(t);
        float sp = sinf(p), cp = cosf(p);
        dirs[tid] = make_float4(st * sp, ct, st * cp, log2f(st));
    }
    for (int i = tid; i < NDIR * NKP; i += BLOCK) {
        int d = i / NKP;
        int k = i - d * NKP;
        basesT[i] = (k < NK) ? bases[k * NDIR + d] : 0.0f;
    }
    __syncthreads();

    const int b = blockIdx.z;
    const int p = blockIdx.x * BLOCK + tid;

    const int ix = p & (NGRID - 1);
    const int iy = (p >> 7) & (NGRID - 1);
    const int iz = p >> 14;
    const float step = 2.0f / 127.0f;
    const float x = -1.0f + ix * step;
    const float y = -1.0f + iy * step;
    const float z = -1.0f + iz * step;

    const int iternum = *iternum_p;
    const float ph0 = (float)((double)(iternum * B + b) * 2.0 * 3.1415926 / 131.0);
    const float lx = sinf(ph0) * 0.3f;
    const float lz = 0.4f;

    const float ldx = lx - x;
    const float ldy = -y;
    const float ldz = lz - z;
    const float s  = fmaf(ldx, ldx, fmaf(ldy, ldy, fmaf(ldz, ldz, 1e-4f)));
    const float rn = rsqrtf(s);
    const float nx = ldx * rn;
    const float ny = ldy * rn;
    const float nz = ldz * rn;

    // ---- Pass 1: normalization sum ----
    float sum = 0.0f;
    #pragma unroll 4
    for (int d = 0; d < NDIR; ++d) {
        float4 v = dirs[d];
        float dp = fmaf(v.x, nx, fmaf(v.y, ny, v.z * nz));
        sum += dir_weight(dp, v.w);
    }

    const float invs = 4.0f / (s * sum);

    // ---- Pass 2: recompute weight, log2, project (k-packed FFMA2) ----
    unsigned long long acc[13];
    #pragma unroll
    for (int j = 0; j < 13; ++j) acc[j] = 0ULL;

    #pragma unroll 2
    for (int d = 0; d < NDIR; ++d) {
        float4 v = dirs[d];
        float dp = fmaf(v.x, nx, fmaf(v.y, ny, v.z * nz));
        float w  = dir_weight(dp, v.w);
        float lg = lg2f(fmaf(w, invs, 1e-4f));   // log2; ln2 folded into SCALE_LN2
        unsigned long long lg2v = pack2(lg, lg);

        const ulonglong2* row = reinterpret_cast<const ulonglong2*>(&basesT[d * NKP]);
        #pragma unroll
        for (int j = 0; j < 6; ++j) {
            ulonglong2 bp = row[j];                  // LDS.128, broadcast
            acc[2*j]   = fma2(bp.x, lg2v, acc[2*j]);
            acc[2*j+1] = fma2(bp.y, lg2v, acc[2*j+1]);
        }
        ulonglong2 bp6 = row[6];
        acc[12] = fma2(bp6.x, lg2v, acc[12]);
    }

    // ---- Epilogue ----
    float res[26];
    #pragma unroll
    for (int j = 0; j < 13; ++j) unpack2(acc[j], res[2*j], res[2*j+1]);

    const size_t PP = (size_t)P_TOTAL;
    float* ob = out + (size_t)b * 75 * PP + p;
    #pragma unroll
    for (int k = 0; k < NK; ++k) {
        float vv = res[k] * SCALE_LN2;
        ob[(size_t)(3 * k + 0) * PP] = vv;
        ob[(size_t)(3 * k + 1) * PP] = vv;
        ob[(size_t)(3 * k + 2) * PP] = vv;
    }
}

extern "C" void kernel_launch(void* const* d_in, const int* in_sizes, int n_in,
                              void* d_out, int out_size)
{
    const float* bases = (const float*)d_in[0];
    const float* th    = (const float*)d_in[1];
    const float* ph    = (const float*)d_in[2];
    const int*   itn   = (const int*)d_in[3];
    const int    B     = in_sizes[4];

    dim3 grid(P_TOTAL / BLOCK, 1, (unsigned)B);
    sh_nearfield_kernel<<<grid, BLOCK>>>(bases, th, ph, itn, B, (float*)d_out);
}

// round 4
// speedup vs baseline: 1.4857x; 1.0962x over previous
#include <cuda_runtime.h>
#include <cuda_bf16.h>
#include <math.h>

#define NGRID 128
#define NDIR  128
#define NK    25
#define NKP   28
#define P_TOTAL (NGRID*NGRID*NGRID)
#define BLOCK 256
#define PPT   2                      // points per thread

#define SCALE_LN2  0.05344600f       // (pi^2/128) * ln2
#define K16LOG2E   23.0831207f       // 16*log2(e)

// q(x) ~ acos(x)^2/(1-x), degree 9
#define C0  2.4674011f
#define C1 -0.6741820f
#define C2  0.3255883f
#define C3 -0.1958168f
#define C4  0.1265018f
#define C5 -0.0758715f
#define C6  0.0363039f
#define C7 -0.0129701f
#define C8  0.0043979f
#define C9 -0.0019498f

typedef unsigned long long u64;

__device__ __forceinline__ float ex2f(float x) {
    float r; asm("ex2.approx.ftz.f32 %0, %1;" : "=f"(r) : "f"(x)); return r;
}
__device__ __forceinline__ float lg2f(float x) {
    float r; asm("lg2.approx.ftz.f32 %0, %1;" : "=f"(r) : "f"(x)); return r;
}
__device__ __forceinline__ u64 pack2(float lo, float hi) {
    u64 r; asm("mov.b64 %0, {%1, %2};" : "=l"(r) : "f"(lo), "f"(hi)); return r;
}
__device__ __forceinline__ void unpack2(u64 v, float& lo, float& hi) {
    asm("mov.b64 {%0, %1}, %2;" : "=f"(lo), "=f"(hi) : "l"(v));
}
__device__ __forceinline__ u64 fma2(u64 a, u64 b, u64 c) {
    u64 d; asm("fma.rn.f32x2 %0, %1, %2, %3;" : "=l"(d) : "l"(a), "l"(b), "l"(c)); return d;
}

__global__ __launch_bounds__(BLOCK)
void sh_nearfield_kernel(const float* __restrict__ bases,
                         const float* __restrict__ th,
                         const float* __restrict__ ph,
                         const int*   __restrict__ iternum_p,
                         int B,
                         float* __restrict__ out)
{
    __shared__ float4 dirs[NDIR];                       // vx, vy, vz, log2(sinth)
    __shared__ __align__(16) float basesT[NDIR * NKP];  // [d][k] padded rows

    const int tid = threadIdx.x;

    if (tid < NDIR) {
        float t = th[tid];
        float p = ph[tid];
        float st = sinf(t), ct = cosf(t);
        float sp = sinf(p), cp = cosf(p);
        dirs[tid] = make_float4(st * sp, ct, st * cp, log2f(st));
    }
    for (int i = tid; i < NDIR * NKP; i += BLOCK) {
        int d = i / NKP;
        int k = i - d * NKP;
        basesT[i] = (k < NK) ? bases[k * NDIR + d] : 0.0f;
    }
    __syncthreads();

    const int b  = blockIdx.z;
    const int p0 = blockIdx.x * (BLOCK * PPT) + tid;
    const int p1 = p0 + BLOCK;

    // light position
    const int iternum = *iternum_p;
    const float ph0 = (float)((double)(iternum * B + b) * 2.0 * 3.1415926 / 131.0);
    const float lx = sinf(ph0) * 0.3f;
    const float lz = 0.4f;

    const float step = 2.0f / 127.0f;

    float nx[PPT], ny[PPT], nz[PPT], ss[PPT];
    {
        const int pp[PPT] = {p0, p1};
        #pragma unroll
        for (int i = 0; i < PPT; ++i) {
            int p = pp[i];
            float x = -1.0f + (p & (NGRID - 1)) * step;
            float y = -1.0f + ((p >> 7) & (NGRID - 1)) * step;
            float z = -1.0f + (p >> 14) * step;
            float ldx = lx - x, ldy = -y, ldz = lz - z;
            float s = fmaf(ldx, ldx, fmaf(ldy, ldy, fmaf(ldz, ldz, 1e-4f)));
            float rn = rsqrtf(s);
            nx[i] = ldx * rn; ny[i] = ldy * rn; nz[i] = ldz * rn;
            ss[i] = s;
        }
    }

    // packed constants (thread-invariant)
    const u64 P9 = pack2(C9, C9), P8 = pack2(C8, C8), P7 = pack2(C7, C7);
    const u64 P6 = pack2(C6, C6), P5 = pack2(C5, C5), P4 = pack2(C4, C4);
    const u64 P3 = pack2(C3, C3), P2 = pack2(C2, C2), P1 = pack2(C1, C1);
    const u64 P0 = pack2(C0, C0);
    const u64 KP = pack2(K16LOG2E, K16LOG2E);
    const u64 KN = pack2(-K16LOG2E, -K16LOG2E);

    // ---- Pass 1: normalization sums ----
    float sum0 = 0.0f, sum1 = 0.0f;
    #pragma unroll 2
    for (int d = 0; d < NDIR; ++d) {
        float4 v = dirs[d];
        float dp0 = fmaf(v.x, nx[0], fmaf(v.y, ny[0], v.z * nz[0]));
        float dp1 = fmaf(v.x, nx[1], fmaf(v.y, ny[1], v.z * nz[1]));
        u64 xc = pack2(fminf(dp0, 0.999f), fminf(dp1, 0.999f));
        u64 q = fma2(P9, xc, P8);
        q = fma2(q, xc, P7); q = fma2(q, xc, P6); q = fma2(q, xc, P5);
        q = fma2(q, xc, P4); q = fma2(q, xc, P3); q = fma2(q, xc, P2);
        q = fma2(q, xc, P1); q = fma2(q, xc, P0);
        u64 up  = fma2(xc, KP, KN);
        u64 lsw = pack2(v.w, v.w);
        u64 arg = fma2(up, q, lsw);
        float a0, a1; unpack2(arg, a0, a1);
        sum0 += ex2f(a0);
        sum1 += ex2f(a1);
    }

    const float invs0 = 4.0f / (ss[0] * sum0);
    const float invs1 = 4.0f / (ss[1] * sum1);

    // ---- Pass 2: recompute weights, log2, project (k-packed FFMA2, shared bases loads) ----
    u64 acc0[13], acc1[13];
    #pragma unroll
    for (int j = 0; j < 13; ++j) { acc0[j] = 0ULL; acc1[j] = 0ULL; }

    #pragma unroll 2
    for (int d = 0; d < NDIR; ++d) {
        float4 v = dirs[d];
        float dp0 = fmaf(v.x, nx[0], fmaf(v.y, ny[0], v.z * nz[0]));
        float dp1 = fmaf(v.x, nx[1], fmaf(v.y, ny[1], v.z * nz[1]));
        u64 xc = pack2(fminf(dp0, 0.999f), fminf(dp1, 0.999f));
        u64 q = fma2(P9, xc, P8);
        q = fma2(q, xc, P7); q = fma2(q, xc, P6); q = fma2(q, xc, P5);
        q = fma2(q, xc, P4); q = fma2(q, xc, P3); q = fma2(q, xc, P2);
        q = fma2(q, xc, P1); q = fma2(q, xc, P0);
        u64 up  = fma2(xc, KP, KN);
        u64 lsw = pack2(v.w, v.w);
        u64 arg = fma2(up, q, lsw);
        float a0, a1; unpack2(arg, a0, a1);
        float w0 = ex2f(a0);
        float w1 = ex2f(a1);
        float lg0 = lg2f(fmaf(w0, invs0, 1e-4f));
        float lg1 = lg2f(fmaf(w1, invs1, 1e-4f));
        u64 lgd0 = pack2(lg0, lg0);
        u64 lgd1 = pack2(lg1, lg1);

        const ulonglong2* row = reinterpret_cast<const ulonglong2*>(&basesT[d * NKP]);
        #pragma unroll
        for (int j = 0; j < 6; ++j) {
            ulonglong2 bp = row[j];                  // LDS.128 broadcast, shared by both points
            acc0[2*j]   = fma2(bp.x, lgd0, acc0[2*j]);
            acc1[2*j]   = fma2(bp.x, lgd1, acc1[2*j]);
            acc0[2*j+1] = fma2(bp.y, lgd0, acc0[2*j+1]);
            acc1[2*j+1] = fma2(bp.y, lgd1, acc1[2*j+1]);
        }
        ulonglong2 bp6 = row[6];
        acc0[12] = fma2(bp6.x, lgd0, acc0[12]);
        acc1[12] = fma2(bp6.x, lgd1, acc1[12]);
    }

    // ---- Epilogue ----
    const size_t PP = (size_t)P_TOTAL;
    float* ob0 = out + (size_t)b * 75 * PP + p0;
    float* ob1 = out + (size_t)b * 75 * PP + p1;

    float r0[26], r1[26];
    #pragma unroll
    for (int j = 0; j < 13; ++j) {
        unpack2(acc0[j], r0[2*j], r0[2*j+1]);
        unpack2(acc1[j], r1[2*j], r1[2*j+1]);
    }
    #pragma unroll
    for (int k = 0; k < NK; ++k) {
        float v0 = r0[k] * SCALE_LN2;
        float v1 = r1[k] * SCALE_LN2;
        size_t o0 = (size_t)(3 * k) * PP;
        ob0[o0]          = v0;  ob1[o0]          = v1;
        ob0[o0 + PP]     = v0;  ob1[o0 + PP]     = v1;
        ob0[o0 + 2 * PP] = v0;  ob1[o0 + 2 * PP] = v1;
    }
}

extern "C" void kernel_launch(void* const* d_in, const int* in_sizes, int n_in,
                              void* d_out, int out_size)
{
    const float* bases = (const float*)d_in[0];
    const float* th    = (const float*)d_in[1];
    const float* ph    = (const float*)d_in[2];
    const int*   itn   = (const int*)d_in[3];
    const int    B     = in_sizes[4];

    dim3 grid(P_TOTAL / (BLOCK * PPT), 1, (unsigned)B);
    sh_nearfield_kernel<<<grid, BLOCK>>>(bases, th, ph, itn, B, (float*)d_out);
}

// round 5
// speedup vs baseline: 1.6366x; 1.1016x over previous
#include <cuda_runtime.h>
#include <cuda_bf16.h>
#include <math.h>

#define NGRID 128
#define NDIR  128
#define NK    25
#define NKP   28
#define P_TOTAL (NGRID*NGRID*NGRID)
#define BLOCK 128
#define PPT   2

#define SCALE_LN2  0.05344600f      // (pi^2/128) * ln2
#define K16LOG2E   23.0831207f      // 16*log2(e)
#define HMIN       0.00200033f      // acos(0.999)^2  (upper clip in h-domain)

// h(x) ~ acos(x)^2, degree-6 monomial on x in [0,1]; benign extrapolation to -1
#define A0f  2.46613525f
#define A1f -3.12988405f
#define A2f  0.95262957f
#define A3f -0.41216060f
#define A4f  0.16084943f
#define A5f -0.04312660f
#define A6f  0.00555700f

typedef unsigned long long u64;

__device__ __forceinline__ float ex2f(float x) {
    float r; asm("ex2.approx.ftz.f32 %0, %1;" : "=f"(r) : "f"(x)); return r;
}
__device__ __forceinline__ float lg2f(float x) {
    float r; asm("lg2.approx.ftz.f32 %0, %1;" : "=f"(r) : "f"(x)); return r;
}
__device__ __forceinline__ u64 pack2(float lo, float hi) {
    u64 r; asm("mov.b64 %0, {%1, %2};" : "=l"(r) : "f"(lo), "f"(hi)); return r;
}
__device__ __forceinline__ void unpack2(u64 v, float& lo, float& hi) {
    asm("mov.b64 {%0, %1}, %2;" : "=f"(lo), "=f"(hi) : "l"(v));
}
__device__ __forceinline__ u64 fma2(u64 a, u64 b, u64 c) {
    u64 d; asm("fma.rn.f32x2 %0, %1, %2, %3;" : "=l"(d) : "l"(a), "l"(b), "l"(c)); return d;
}
__device__ __forceinline__ u64 mul2(u64 a, u64 b) {
    u64 d; asm("mul.rn.f32x2 %0, %1, %2;" : "=l"(d) : "l"(a), "l"(b)); return d;
}

__global__ __launch_bounds__(BLOCK, 6)
void sh_nearfield_kernel(const float* __restrict__ bases,
                         const float* __restrict__ th,
                         const float* __restrict__ ph,
                         const int*   __restrict__ iternum_p,
                         int B,
                         float* __restrict__ out)
{
    __shared__ __align__(16) float4 D1[NDIR];            // {vx,vx,vy,vy}
    __shared__ __align__(16) float4 D2[NDIR];            // {vz,vz,lsw,0}
    __shared__ __align__(16) float  basesT[NDIR * NKP];  // [d][k] padded rows

    const int tid = threadIdx.x;

    {   // BLOCK == NDIR: each thread fills one direction
        float t = th[tid];
        float p = ph[tid];
        float st = sinf(t), ct = cosf(t);
        float sp = sinf(p), cp = cosf(p);
        float vx = st * sp, vy = ct, vz = st * cp;
        float lsw = log2f(st);
        D1[tid] = make_float4(vx, vx, vy, vy);
        D2[tid] = make_float4(vz, vz, lsw, 0.0f);
    }
    for (int i = tid; i < NDIR * NKP; i += BLOCK) {
        int d = i / NKP;
        int k = i - d * NKP;
        basesT[i] = (k < NK) ? bases[k * NDIR + d] : 0.0f;
    }
    __syncthreads();

    const int b  = blockIdx.z;
    const int p0 = blockIdx.x * (BLOCK * PPT) + 2 * tid;   // adjacent pair
    const int p1 = p0 + 1;

    const int iternum = *iternum_p;
    const float ph0 = (float)((double)(iternum * B + b) * 2.0 * 3.1415926 / 131.0);
    const float lx = sinf(ph0) * 0.3f;
    const float lz = 0.4f;
    const float step = 2.0f / 127.0f;

    float s0, s1;
    u64 nx2, ny2, nz2;
    {
        float nx[2], ny[2], nz[2], ssv[2];
        const int pp[2] = {p0, p1};
        #pragma unroll
        for (int i = 0; i < 2; ++i) {
            int p = pp[i];
            float x = -1.0f + (p & (NGRID - 1)) * step;
            float y = -1.0f + ((p >> 7) & (NGRID - 1)) * step;
            float z = -1.0f + (p >> 14) * step;
            float ldx = lx - x, ldy = -y, ldz = lz - z;
            float s = fmaf(ldx, ldx, fmaf(ldy, ldy, fmaf(ldz, ldz, 1e-4f)));
            float rn = rsqrtf(s);
            nx[i] = ldx * rn; ny[i] = ldy * rn; nz[i] = ldz * rn;
            ssv[i] = s;
        }
        nx2 = pack2(nx[0], nx[1]);
        ny2 = pack2(ny[0], ny[1]);
        nz2 = pack2(nz[0], nz[1]);
        s0 = ssv[0]; s1 = ssv[1];
    }

    const u64 PA0 = pack2(A0f, A0f), PA1 = pack2(A1f, A1f), PA2 = pack2(A2f, A2f);
    const u64 PA3 = pack2(A3f, A3f), PA4 = pack2(A4f, A4f), PA5 = pack2(A5f, A5f);
    const u64 PA6 = pack2(A6f, A6f);

#define DIR_ARGS(d, a0, a1)                                                    \
    {                                                                          \
        ulonglong2 u1 = *reinterpret_cast<const ulonglong2*>(&D1[d]);          \
        ulonglong2 u2 = *reinterpret_cast<const ulonglong2*>(&D2[d]);          \
        u64 dp2 = fma2(u1.x, nx2, fma2(u1.y, ny2, mul2(u2.x, nz2)));           \
        u64 h2 = fma2(PA6, dp2, PA5);                                          \
        h2 = fma2(h2, dp2, PA4);                                               \
        h2 = fma2(h2, dp2, PA3);                                               \
        h2 = fma2(h2, dp2, PA2);                                               \
        h2 = fma2(h2, dp2, PA1);                                               \
        h2 = fma2(h2, dp2, PA0);                                               \
        float h0, h1; unpack2(h2, h0, h1);                                     \
        float lsw = __uint_as_float((unsigned)u2.y);                           \
        a0 = fmaf(fmaxf(h0, HMIN), -K16LOG2E, lsw);                            \
        a1 = fmaf(fmaxf(h1, HMIN), -K16LOG2E, lsw);                            \
    }

    // ---- Pass 1: normalization sums ----
    float sum0 = 0.0f, sum1 = 0.0f;
    #pragma unroll 2
    for (int d = 0; d < NDIR; ++d) {
        float a0, a1;
        DIR_ARGS(d, a0, a1);
        sum0 += ex2f(a0);
        sum1 += ex2f(a1);
    }

    const float invs0 = 4.0f / (s0 * sum0);
    const float invs1 = 4.0f / (s1 * sum1);

    // ---- Pass 2: recompute weights, log2, project (k-packed FFMA2) ----
    u64 acc0[13], acc1[13];
    #pragma unroll
    for (int j = 0; j < 13; ++j) { acc0[j] = 0ULL; acc1[j] = 0ULL; }

    #pragma unroll 2
    for (int d = 0; d < NDIR; ++d) {
        float a0, a1;
        DIR_ARGS(d, a0, a1);
        float w0 = ex2f(a0);
        float w1 = ex2f(a1);
        float lg0 = lg2f(fmaf(w0, invs0, 1e-4f));
        float lg1 = lg2f(fmaf(w1, invs1, 1e-4f));
        u64 lgd0 = pack2(lg0, lg0);
        u64 lgd1 = pack2(lg1, lg1);

        const ulonglong2* row = reinterpret_cast<const ulonglong2*>(&basesT[d * NKP]);
        #pragma unroll
        for (int j = 0; j < 6; ++j) {
            ulonglong2 bp = row[j];                  // LDS.128 broadcast, shared by both points
            acc0[2*j]   = fma2(bp.x, lgd0, acc0[2*j]);
            acc1[2*j]   = fma2(bp.x, lgd1, acc1[2*j]);
            acc0[2*j+1] = fma2(bp.y, lgd0, acc0[2*j+1]);
            acc1[2*j+1] = fma2(bp.y, lgd1, acc1[2*j+1]);
        }
        ulonglong2 bp6 = row[6];
        acc0[12] = fma2(bp6.x, lgd0, acc0[12]);
        acc1[12] = fma2(bp6.x, lgd1, acc1[12]);
    }

    // ---- Epilogue: adjacent points -> coalesced float2 stores ----
    const size_t PP = (size_t)P_TOTAL;
    float* ob = out + (size_t)b * 75 * PP + p0;

    float r0[26], r1[26];
    #pragma unroll
    for (int j = 0; j < 13; ++j) {
        unpack2(acc0[j], r0[2*j], r0[2*j+1]);
        unpack2(acc1[j], r1[2*j], r1[2*j+1]);
    }
    #pragma unroll
    for (int k = 0; k < NK; ++k) {
        float2 vv = make_float2(r0[k] * SCALE_LN2, r1[k] * SCALE_LN2);
        size_t o0 = (size_t)(3 * k) * PP;
        *reinterpret_cast<float2*>(ob + o0)          = vv;
        *reinterpret_cast<float2*>(ob + o0 + PP)     = vv;
        *reinterpret_cast<float2*>(ob + o0 + 2 * PP) = vv;
    }
#undef DIR_ARGS
}

extern "C" void kernel_launch(void* const* d_in, const int* in_sizes, int n_in,
                              void* d_out, int out_size)
{
    const float* bases = (const float*)d_in[0];
    const float* th    = (const float*)d_in[1];
    const float* ph    = (const float*)d_in[2];
    const int*   itn   = (const int*)d_in[3];
    const int    B     = in_sizes[4];

    dim3 grid(P_TOTAL / (BLOCK * PPT), 1, (unsigned)B);
    sh_nearfield_kernel<<<grid, BLOCK>>>(bases, th, ph, itn, B, (float*)d_out);
}

// round 6
// speedup vs baseline: 2.0349x; 1.2434x over previous
#include <cuda_runtime.h>
#include <cuda_bf16.h>
#include <math.h>

#define NGRID 128
#define NDIR  128
#define NK    25
#define P_TOTAL (NGRID*NGRID*NGRID)
#define BLOCK 128
#define CHUNK 16
#define NCH   (NDIR/CHUNK)

#define SCALE_LN2  0.05344600f      // (pi^2/128) * ln2
#define K16LOG2E   23.0831207f      // 16*log2(e)
#define HMIN       0.00200033f      // acos(0.999)^2

// h(x) ~ acos(x)^2, degree-6 monomial
#define A0f  2.46613525f
#define A1f -3.12988405f
#define A2f  0.95262957f
#define A3f -0.41216060f
#define A4f  0.16084943f
#define A5f -0.04312660f
#define A6f  0.00555700f

#define BSTRIDE 132   // bases smem row stride (conflict-free A-frag reads)
#define LSTRIDE 72    // lg smem row stride (conflict-free B-frag reads)

typedef unsigned long long u64;
typedef unsigned int u32;

__device__ __forceinline__ float ex2f(float x) {
    float r; asm("ex2.approx.ftz.f32 %0, %1;" : "=f"(r) : "f"(x)); return r;
}
__device__ __forceinline__ float lg2f(float x) {
    float r; asm("lg2.approx.ftz.f32 %0, %1;" : "=f"(r) : "f"(x)); return r;
}
__device__ __forceinline__ u64 pack2(float lo, float hi) {
    u64 r; asm("mov.b64 %0, {%1, %2};" : "=l"(r) : "f"(lo), "f"(hi)); return r;
}
__device__ __forceinline__ void unpack2(u64 v, float& lo, float& hi) {
    asm("mov.b64 {%0, %1}, %2;" : "=f"(lo), "=f"(hi) : "l"(v));
}
__device__ __forceinline__ u64 fma2(u64 a, u64 b, u64 c) {
    u64 d; asm("fma.rn.f32x2 %0, %1, %2, %3;" : "=l"(d) : "l"(a), "l"(b), "l"(c)); return d;
}
__device__ __forceinline__ u64 mul2(u64 a, u64 b) {
    u64 d; asm("mul.rn.f32x2 %0, %1, %2;" : "=l"(d) : "l"(a), "l"(b)); return d;
}
__device__ __forceinline__ u32 tf32b(float x) {
    u32 r; asm("cvt.rna.tf32.f32 %0, %1;" : "=r"(r) : "f"(x)); return r;
}
__device__ __forceinline__ void mma_tf32(float& c0, float& c1, float& c2, float& c3,
                                         u32 a0, u32 a1, u32 a2, u32 a3,
                                         u32 b0, u32 b1) {
    asm("mma.sync.aligned.m16n8k8.row.col.f32.tf32.tf32.f32 "
        "{%0,%1,%2,%3}, {%4,%5,%6,%7}, {%8,%9}, {%0,%1,%2,%3};"
        : "+f"(c0), "+f"(c1), "+f"(c2), "+f"(c3)
        : "r"(a0), "r"(a1), "r"(a2), "r"(a3), "r"(b0), "r"(b1));
}

__global__ __launch_bounds__(BLOCK, 4)
void sh_nearfield_kernel(const float* __restrict__ bases,
                         const float* __restrict__ th,
                         const float* __restrict__ ph,
                         const int*   __restrict__ iternum_p,
                         int B,
                         float* __restrict__ out)
{
    __shared__ __align__(16) float4 D1[NDIR];            // {vx,vx,vy,vy}
    __shared__ __align__(16) float4 D2[NDIR];            // {vz,vz,lsw,0}
    __shared__ u32 basesM[32 * BSTRIDE];                 // tf32 bits, [m][d]
    __shared__ u32 lgS[4 * CHUNK * LSTRIDE];             // per-warp lg tiles

    const int tid  = threadIdx.x;
    const int w    = tid >> 5;
    const int lane = tid & 31;
    const int g    = lane >> 2;      // groupID
    const int t4   = lane & 3;       // thread-in-group

    {   // one direction per thread
        float t = th[tid];
        float p = ph[tid];
        float st = sinf(t), ct = cosf(t);
        float sp = sinf(p), cp = cosf(p);
        float vx = st * sp, vy = ct, vz = st * cp;
        D1[tid] = make_float4(vx, vx, vy, vy);
        D2[tid] = make_float4(vz, vz, log2f(st), 0.0f);
    }
    for (int i = tid; i < 32 * NDIR; i += BLOCK) {
        int m = i >> 7, d = i & (NDIR - 1);
        float v = (m < NK) ? bases[m * NDIR + d] : 0.0f;
        basesM[m * BSTRIDE + d] = tf32b(v);
    }
    __syncthreads();

    const int b  = blockIdx.z;
    const int p0 = blockIdx.x * (BLOCK * 2) + 2 * tid;

    const int iternum = *iternum_p;
    const float ph0 = (float)((double)(iternum * B + b) * 2.0 * 3.1415926 / 131.0);
    const float lx = sinf(ph0) * 0.3f;
    const float lz = 0.4f;
    const float step = 2.0f / 127.0f;

    float s0, s1;
    u64 nx2, ny2, nz2;
    {
        float nx[2], ny[2], nz[2], ssv[2];
        #pragma unroll
        for (int i = 0; i < 2; ++i) {
            int p = p0 + i;
            float x = -1.0f + (p & (NGRID - 1)) * step;
            float y = -1.0f + ((p >> 7) & (NGRID - 1)) * step;
            float z = -1.0f + (p >> 14) * step;
            float ldx = lx - x, ldy = -y, ldz = lz - z;
            float s = fmaf(ldx, ldx, fmaf(ldy, ldy, fmaf(ldz, ldz, 1e-4f)));
            float rn = rsqrtf(s);
            nx[i] = ldx * rn; ny[i] = ldy * rn; nz[i] = ldz * rn;
            ssv[i] = s;
        }
        nx2 = pack2(nx[0], nx[1]);
        ny2 = pack2(ny[0], ny[1]);
        nz2 = pack2(nz[0], nz[1]);
        s0 = ssv[0]; s1 = ssv[1];
    }

    const u64 PA0 = pack2(A0f, A0f), PA1 = pack2(A1f, A1f), PA2 = pack2(A2f, A2f);
    const u64 PA3 = pack2(A3f, A3f), PA4 = pack2(A4f, A4f), PA5 = pack2(A5f, A5f);
    const u64 PA6 = pack2(A6f, A6f);

#define DIR_ARGS(d, a0v, a1v)                                                  \
    {                                                                          \
        ulonglong2 u1 = *reinterpret_cast<const ulonglong2*>(&D1[d]);          \
        ulonglong2 u2 = *reinterpret_cast<const ulonglong2*>(&D2[d]);          \
        u64 dp2 = fma2(u1.x, nx2, fma2(u1.y, ny2, mul2(u2.x, nz2)));           \
        u64 h2 = fma2(PA6, dp2, PA5);                                          \
        h2 = fma2(h2, dp2, PA4);                                               \
        h2 = fma2(h2, dp2, PA3);                                               \
        h2 = fma2(h2, dp2, PA2);                                               \
        h2 = fma2(h2, dp2, PA1);                                               \
        h2 = fma2(h2, dp2, PA0);                                               \
        float h0, h1; unpack2(h2, h0, h1);                                     \
        float lsw = __uint_as_float((unsigned)u2.y);                           \
        a0v = fmaf(fmaxf(h0, HMIN), -K16LOG2E, lsw);                           \
        a1v = fmaf(fmaxf(h1, HMIN), -K16LOG2E, lsw);                           \
    }

    // ---- Pass 1: normalization sums ----
    float sum0 = 0.0f, sum1 = 0.0f;
    #pragma unroll 2
    for (int d = 0; d < NDIR; ++d) {
        float a0, a1;
        DIR_ARGS(d, a0, a1);
        sum0 += ex2f(a0);
        sum1 += ex2f(a1);
    }
    const float invs0 = 4.0f / (s0 * sum0);
    const float invs1 = 4.0f / (s1 * sum1);

    // ---- Pass 2: lg generation + tensor-core projection, chunked per warp ----
    float C[2][8][4];
    #pragma unroll
    for (int mt = 0; mt < 2; ++mt)
        #pragma unroll
        for (int nt = 0; nt < 8; ++nt)
            #pragma unroll
            for (int q = 0; q < 4; ++q) C[mt][nt][q] = 0.0f;

    u32* lgW = &lgS[w * CHUNK * LSTRIDE];

    for (int ch = 0; ch < NCH; ++ch) {
        #pragma unroll 2
        for (int dl = 0; dl < CHUNK; ++dl) {
            int d = ch * CHUNK + dl;
            float a0, a1;
            DIR_ARGS(d, a0, a1);
            float w0 = ex2f(a0);
            float w1 = ex2f(a1);
            float lg0 = lg2f(fmaf(w0, invs0, 1e-4f));
            float lg1 = lg2f(fmaf(w1, invs1, 1e-4f));
            uint2 u = make_uint2(tf32b(lg0), tf32b(lg1));
            *reinterpret_cast<uint2*>(&lgW[dl * LSTRIDE + 2 * lane]) = u;
        }
        __syncwarp();

        #pragma unroll
        for (int ks = 0; ks < 2; ++ks) {
            const int kcol = ch * CHUNK + ks * 8 + t4;
            u32 a[2][4];
            #pragma unroll
            for (int mt = 0; mt < 2; ++mt) {
                int base = (g + 16 * mt) * BSTRIDE + kcol;
                a[mt][0] = basesM[base];
                a[mt][1] = basesM[base + 8 * BSTRIDE];
                a[mt][2] = basesM[base + 4];
                a[mt][3] = basesM[base + 8 * BSTRIDE + 4];
            }
            #pragma unroll
            for (int nt = 0; nt < 8; ++nt) {
                int bb = (ks * 8 + t4) * LSTRIDE + 8 * nt + g;
                u32 b0 = lgW[bb];
                u32 b1 = lgW[bb + 4 * LSTRIDE];
                mma_tf32(C[0][nt][0], C[0][nt][1], C[0][nt][2], C[0][nt][3],
                         a[0][0], a[0][1], a[0][2], a[0][3], b0, b1);
                mma_tf32(C[1][nt][0], C[1][nt][1], C[1][nt][2], C[1][nt][3],
                         a[1][0], a[1][1], a[1][2], a[1][3], b0, b1);
            }
        }
        __syncwarp();
    }

    // ---- Epilogue: C fragments -> out[b][3k+c][p], replicated x3 ----
    const size_t PP = (size_t)P_TOTAL;
    float* ob = out + (size_t)b * 75 * PP;
    const int pb = blockIdx.x * (BLOCK * 2) + 64 * w;

    #pragma unroll
    for (int mt = 0; mt < 2; ++mt) {
        #pragma unroll
        for (int nt = 0; nt < 8; ++nt) {
            const int pcol = pb + 8 * nt + 2 * t4;
            const int r0 = 16 * mt + g;          // always < 25
            const int r1 = r0 + 8;               // mt=1: 24+g, store only if <25
            float2 v0 = make_float2(C[mt][nt][0] * SCALE_LN2, C[mt][nt][1] * SCALE_LN2);
            float2 v1 = make_float2(C[mt][nt][2] * SCALE_LN2, C[mt][nt][3] * SCALE_LN2);
            #pragma unroll
            for (int c = 0; c < 3; ++c) {
                *reinterpret_cast<float2*>(ob + (size_t)(3 * r0 + c) * PP + pcol) = v0;
            }
            if (r1 < NK) {
                #pragma unroll
                for (int c = 0; c < 3; ++c) {
                    *reinterpret_cast<float2*>(ob + (size_t)(3 * r1 + c) * PP + pcol) = v1;
                }
            }
        }
    }
#undef DIR_ARGS
}

extern "C" void kernel_launch(void* const* d_in, const int* in_sizes, int n_in,
                              void* d_out, int out_size)
{
    const float* bases = (const float*)d_in[0];
    const float* th    = (const float*)d_in[1];
    const float* ph    = (const float*)d_in[2];
    const int*   itn   = (const int*)d_in[3];
    const int    B     = in_sizes[4];

    dim3 grid(P_TOTAL / (BLOCK * 2), 1, (unsigned)B);
    sh_nearfield_kernel<<<grid, BLOCK>>>(bases, th, ph, itn, B, (float*)d_out);
}